// round 15
// baseline (speedup 1.0000x reference)
#include <cuda_runtime.h>

#define N_NODES 20000
#define N_EDGES 200000
#define D 32
#define R 100
#define EPS 1e-5f
#define NB 400          // histogram/scatter blocks
#define EPB 500         // edges per block (NB*EPB == N_EDGES)
#define FULL 0xffffffffu

// ---------------- device scratch (static, no runtime allocation) --------
__device__ int   g_dcnt[N_NODES];           // per-dst counts (self-zeroing)
__device__ int   g_doff[N_NODES + 1];       // CSR offsets by dst
__device__ int   g_dcur[N_NODES];           // scatter cursors by dst
__device__ int   g_bh[R * NB];              // per-(relation, block) histogram
__device__ int   g_boff[R * NB];            // per-(relation, block) base offset
__device__ int   g_hist[R];                 // per-relation totals
__device__ int   g_off[R + 1];              // relation bases
__device__ int   g_chunkbase[R + 1];        // chunk-count scan
__device__ int   g_ssrc[N_EDGES];           // src sorted by etype
__device__ int   g_posOf[N_EDGES];          // etype-sorted position of edge e
__device__ int   g_eidx2[N_EDGES];          // msg-positions grouped by dst
__device__ float g_msg[N_EDGES * D];        // relu(h[src] @ W[etype]), etype order
__device__ float g_sum[D], g_sumsq[D];
__device__ int   g_nchunk;

// ---------------- K1: per-block etype histograms + global dst histogram --
__global__ void __launch_bounds__(256) k1_hist(const int* __restrict__ etype,
                                               const int* __restrict__ dst) {
    __shared__ int sh[R];
    for (int i = threadIdx.x; i < R; i += blockDim.x) sh[i] = 0;
    __syncthreads();
    int base = blockIdx.x * EPB;
    for (int i = threadIdx.x; i < EPB; i += blockDim.x) {
        atomicAdd(&sh[etype[base + i]], 1);
        atomicAdd(&g_dcnt[dst[base + i]], 1);   // 20K spread addrs: cheap
    }
    __syncthreads();
    for (int r = threadIdx.x; r < R; r += blockDim.x)
        g_bh[r * NB + blockIdx.x] = sh[r];
}

// ---------------- KS: both scans in one kernel, 2 independent blocks -----
// block 0: etype scans (relation totals, bases, per-block offsets)
// block 1: dst-count scan (two-pass, spill-free) + zero g_sum/g_sumsq
__global__ void __launch_bounds__(1024) ks_scan() {
    __shared__ int wsum[32], wbase[32];
    const int lane = threadIdx.x & 31;
    const int wid  = threadIdx.x >> 5;
    const int tid  = threadIdx.x;

    if (blockIdx.x == 0) {
        // ---- phase 1: per-relation totals (warp-per-relation reduce) ----
        for (int r = wid; r < R; r += 32) {
            int s = 0;
            for (int b = lane; b < NB; b += 32) s += g_bh[r * NB + b];
#pragma unroll
            for (int d = 16; d > 0; d >>= 1) s += __shfl_down_sync(FULL, s, d);
            if (lane == 0) g_hist[r] = s;
        }
        __syncthreads();

        // ---- phase 2: scan relation totals + chunk counts (warp 0) ----
        if (wid == 0) {
            int acc = 0, cacc = 0;
            for (int base = 0; base < R; base += 32) {
                int r = base + lane;
                int hv = (r < R) ? g_hist[r] : 0;
                int cv = (hv + 31) >> 5;
                int hs = hv, cs = cv;
#pragma unroll
                for (int d = 1; d < 32; d <<= 1) {
                    int t1 = __shfl_up_sync(FULL, hs, d);
                    int t2 = __shfl_up_sync(FULL, cs, d);
                    if (lane >= d) { hs += t1; cs += t2; }
                }
                if (r < R) {
                    g_off[r] = acc + hs - hv;
                    g_chunkbase[r] = cacc + cs - cv;
                }
                acc  += __shfl_sync(FULL, hs, 31);
                cacc += __shfl_sync(FULL, cs, 31);
            }
            if (lane == 0) { g_off[R] = acc; g_chunkbase[R] = cacc; g_nchunk = cacc; }
        }
        __syncthreads();

        // ---- phase 3: per-relation scan over blocks (warp/relation) ----
        for (int r = wid; r < R; r += 32) {
            int carry = g_off[r];
            for (int b0 = 0; b0 < NB; b0 += 32) {
                int b = b0 + lane;
                int v = (b < NB) ? g_bh[r * NB + b] : 0;
                int s = v;
#pragma unroll
                for (int d = 1; d < 32; d <<= 1) {
                    int t = __shfl_up_sync(FULL, s, d);
                    if (lane >= d) s += t;
                }
                if (b < NB) g_boff[r * NB + b] = carry + s - v;
                carry += __shfl_sync(FULL, s, 31);
            }
        }
    } else {
        // ================= block 1: dst scan, TWO-PASS (no reg array) ====
        if (tid < D) { g_sum[tid] = 0.f; g_sumsq[tid] = 0.f; }

        const int NPT = 20;                       // 1024*20 >= 20000
        int base_i = tid * NPT;
        // pass 1: sum only (20 independent loads, no array -> no spills)
        int lsum = 0;
#pragma unroll
        for (int j = 0; j < NPT; j++) {
            int i = base_i + j;
            if (i < N_NODES) lsum += g_dcnt[i];
        }
        int s = lsum;
#pragma unroll
        for (int d = 1; d < 32; d <<= 1) {
            int t = __shfl_up_sync(FULL, s, d);
            if (lane >= d) s += t;
        }
        int excl = s - lsum;
        if (lane == 31) wsum[wid] = s;
        __syncthreads();
        if (wid == 0) {
            int v2 = wsum[lane], s2 = v2;
#pragma unroll
            for (int d = 1; d < 32; d <<= 1) {
                int t = __shfl_up_sync(FULL, s2, d);
                if (lane >= d) s2 += t;
            }
            wbase[lane] = s2 - v2;
            if (lane == 31) g_doff[N_NODES] = s2;
        }
        __syncthreads();
        // pass 2: reload values (L2 hits, independent of carry), write, zero
        int run = wbase[wid] + excl;
#pragma unroll
        for (int j = 0; j < NPT; j++) {
            int i = base_i + j;
            if (i < N_NODES) {
                int v = g_dcnt[i];
                g_doff[i] = run;
                g_dcur[i] = run;
                g_dcnt[i] = 0;                    // self-zero for next replay
                run += v;
            }
        }
    }
}

// ---------------- K3: etype scatter ONLY (+ coalesced inverse perm) -------
// dst-side scatter moved into k4's prologue (overlaps with GEMV there).
__global__ void __launch_bounds__(256) k3_scatter(
    const int* __restrict__ etype, const int* __restrict__ src)
{
    __shared__ int cur[R];
    for (int r = threadIdx.x; r < R; r += blockDim.x)
        cur[r] = g_boff[r * NB + blockIdx.x];
    __syncthreads();
    int base = blockIdx.x * EPB;
    for (int i = threadIdx.x; i < EPB; i += blockDim.x) {
        int e = base + i;
        int pos = atomicAdd(&cur[etype[e]], 1);    // shared, low contention
        g_ssrc[pos] = src[e];                      // scattered store
        g_posOf[e] = pos;                          // coalesced store
    }
}

// ---------------- K4: dst-scatter prologue + GEMV (FFMA2) -----------------
// Prologue: each block scatters a 125-edge dst slice (latency hides under
// other warps' GEMV; consumed only by k6 which launches after k4).
// Mainloop: frozen round-11 config (26us floor).
__global__ void __launch_bounds__(128, 8) k4_compute(
    const float* __restrict__ h, const float* __restrict__ weight,
    const int* __restrict__ dst)
{
    __shared__ __align__(16) float tile[4][32][32];
    __shared__ int s_cb[R + 1], s_off[R + 1];
    const int lane = threadIdx.x & 31;
    const int wid  = threadIdx.x >> 5;
    const int warp = (blockIdx.x * blockDim.x + threadIdx.x) >> 5;
    const int nwarp = (gridDim.x * blockDim.x) >> 5;

    // ---- dst-scatter prologue: 125 edges per block, one per thread ----
    {
        int e = blockIdx.x * 125 + threadIdx.x;
        if (threadIdx.x < 125) {
            int dpos = atomicAdd(&g_dcur[dst[e]], 1);   // 20K spread addrs
            g_eidx2[dpos] = g_posOf[e];
        }
    }

    for (int i = threadIdx.x; i <= R; i += blockDim.x) {
        s_cb[i] = g_chunkbase[i];
        s_off[i] = g_off[i];
    }
    __syncthreads();
    const int nchunk = g_nchunk;

    float lsum = 0.f, lsq = 0.f;

    for (int w = warp; w < nchunk; w += nwarp) {
        int lo2 = 0, hi2 = R;                      // largest r: cb[r] <= w
        while (lo2 < hi2) {
            int mid = (lo2 + hi2 + 1) >> 1;
            if (s_cb[mid] <= w) lo2 = mid; else hi2 = mid - 1;
        }
        int r = lo2;
        int s = s_off[r] + ((w - s_cb[r]) << 5);
        int n = min(32, s_off[r + 1] - s);

        // pack W columns for this lane into 16 b64 (f32x2) registers
        const float* wp = weight + r * (D * D) + lane;
        unsigned long long wc2[16];
#pragma unroll
        for (int k = 0; k < 16; k++) {
            float w0 = wp[(2 * k) * 32];
            float w1 = wp[(2 * k + 1) * 32];
            asm("mov.b64 %0, {%1, %2};" : "=l"(wc2[k]) : "f"(w0), "f"(w1));
        }

        int sj = 0;
        if (lane < n) sj = g_ssrc[s + lane];
        for (int j = 0; j < n; j++) {
            int sje = __shfl_sync(FULL, sj, j);
            tile[wid][j][lane] = h[sje * D + lane];   // coalesced 128B
        }
        __syncwarp();

        for (int j = 0; j < n; j++) {
            const ulonglong2* row = (const ulonglong2*)tile[wid][j];
            unsigned long long a0 = 0ull, a1 = 0ull, a2 = 0ull, a3 = 0ull;
#pragma unroll
            for (int kk = 0; kk < 4; kk++) {
                ulonglong2 q0 = row[2 * kk];          // LDS.128 broadcast
                ulonglong2 q1 = row[2 * kk + 1];
                asm("fma.rn.f32x2 %0, %1, %2, %0;" : "+l"(a0) : "l"(q0.x), "l"(wc2[4 * kk + 0]));
                asm("fma.rn.f32x2 %0, %1, %2, %0;" : "+l"(a1) : "l"(q0.y), "l"(wc2[4 * kk + 1]));
                asm("fma.rn.f32x2 %0, %1, %2, %0;" : "+l"(a2) : "l"(q1.x), "l"(wc2[4 * kk + 2]));
                asm("fma.rn.f32x2 %0, %1, %2, %0;" : "+l"(a3) : "l"(q1.y), "l"(wc2[4 * kk + 3]));
            }
            unsigned long long s01, s23, sT;
            asm("add.rn.f32x2 %0, %1, %2;" : "=l"(s01) : "l"(a0), "l"(a1));
            asm("add.rn.f32x2 %0, %1, %2;" : "=l"(s23) : "l"(a2), "l"(a3));
            asm("add.rn.f32x2 %0, %1, %2;" : "=l"(sT)  : "l"(s01), "l"(s23));
            float xlo, xhi;
            asm("mov.b64 {%0, %1}, %2;" : "=f"(xlo), "=f"(xhi) : "l"(sT));
            float acc = fmaxf(xlo + xhi, 0.f);
            lsum += acc;
            lsq = fmaf(acc, acc, lsq);
            g_msg[(s + j) * D + lane] = acc;          // coalesced 128B store
        }
        __syncwarp();
    }
    __shared__ float ssum[4][32], ssq[4][32];
    ssum[wid][lane] = lsum; ssq[wid][lane] = lsq;
    __syncthreads();
    if (wid == 0) {
        float ts = ssum[0][lane] + ssum[1][lane] + ssum[2][lane] + ssum[3][lane];
        float tq = ssq[0][lane] + ssq[1][lane] + ssq[2][lane] + ssq[3][lane];
        atomicAdd(&g_sum[lane], ts);
        atomicAdd(&g_sumsq[lane], tq);
    }
}

// ---------------- K6: gather reduce + folded BN finalize -----------------
__global__ void __launch_bounds__(128) k6_reduce(
    float* __restrict__ out, const float* __restrict__ gamma,
    const float* __restrict__ beta)
{
    __shared__ float s_sc[32], s_sh[32];
    if (threadIdx.x < 32) {
        int d = threadIdx.x;
        float inv_e = 1.0f / (float)N_EDGES;
        float mu = g_sum[d] * inv_e;
        float var = fmaxf(g_sumsq[d] * inv_e - mu * mu, 0.f);
        float scale = rsqrtf(var + EPS) * gamma[d];
        s_sc[d] = scale;
        s_sh[d] = beta[d] - mu * scale;
    }
    __syncthreads();

    const int lane = threadIdx.x & 31;
    const int node = (blockIdx.x * blockDim.x + threadIdx.x) >> 5;
    if (node >= N_NODES) return;
    const float sc = s_sc[lane], shf = s_sh[lane];

    int off = g_doff[node], end = g_doff[node + 1];
    int cnt = end - off;
    float acc = 0.f;
    int i = off;
    for (; i + 1 < end; i += 2) {
        int p0 = g_eidx2[i];
        int p1 = g_eidx2[i + 1];
        acc += g_msg[p0 * D + lane];
        acc += g_msg[p1 * D + lane];
    }
    if (i < end) acc += g_msg[g_eidx2[i] * D + lane];

    float v = 0.f;
    if (cnt > 0) v = fmaf(acc * (1.0f / (float)cnt), sc, shf);
    out[node * D + lane] = v;
}

extern "C" void kernel_launch(void* const* d_in, const int* in_sizes, int n_in,
                              void* d_out, int out_size) {
    const float* h      = (const float*)d_in[0];
    const float* weight = (const float*)d_in[1];
    const float* gamma  = (const float*)d_in[2];
    const float* beta   = (const float*)d_in[3];
    const int*   src    = (const int*)d_in[4];
    const int*   dst    = (const int*)d_in[5];
    const int*   etype  = (const int*)d_in[6];
    float* out = (float*)d_out;

    k1_hist<<<NB, 256>>>(etype, dst);
    ks_scan<<<2, 1024>>>();
    k3_scatter<<<NB, 256>>>(etype, src);
    k4_compute<<<1600, 128>>>(h, weight, dst);
    k6_reduce<<<(N_NODES * 32 + 127) / 128, 128>>>(out, gamma, beta);
}

// round 16
// speedup vs baseline: 1.2357x; 1.2357x over previous
#include <cuda_runtime.h>

#define N_NODES 20000
#define N_EDGES 200000
#define D 32
#define R 100
#define EPS 1e-5f
#define NB 400          // histogram/scatter blocks
#define EPB 500         // edges per block (NB*EPB == N_EDGES)
#define FULL 0xffffffffu

// ---------------- device scratch (static, no runtime allocation) --------
__device__ int   g_dcnt[N_NODES];           // per-dst counts (zeroed by k6)
__device__ int   g_bh[R * NB];              // per-(relation, block) histogram
__device__ int   g_boff[R * NB];            // per-(relation, block) base offset
__device__ int   g_hist[R];                 // per-relation totals
__device__ int   g_off[R + 1];              // relation bases
__device__ int   g_chunkbase[R + 1];        // chunk-count scan
__device__ int   g_ssrc[N_EDGES];           // src sorted by etype
__device__ int   g_sdst[N_EDGES];           // dst sorted by etype
__device__ float g_sum[D], g_sumsq[D];
__device__ int   g_nchunk;

// ---------------- K1: histograms + zero the output accumulator -----------
__global__ void __launch_bounds__(256) k1_hist(const int* __restrict__ etype,
                                               const int* __restrict__ dst,
                                               float* __restrict__ out) {
    __shared__ int sh[R];
    for (int i = threadIdx.x; i < R; i += blockDim.x) sh[i] = 0;
    // zero this block's slice of out (N_NODES*D / NB = 1600 floats)
    {
        float4* o4 = (float4*)(out) + blockIdx.x * 400;
        for (int i = threadIdx.x; i < 400; i += blockDim.x)
            o4[i] = make_float4(0.f, 0.f, 0.f, 0.f);
    }
    __syncthreads();
    int base = blockIdx.x * EPB;
    for (int i = threadIdx.x; i < EPB; i += blockDim.x) {
        atomicAdd(&sh[etype[base + i]], 1);
        atomicAdd(&g_dcnt[dst[base + i]], 1);   // 20K spread addrs: cheap
    }
    __syncthreads();
    for (int r = threadIdx.x; r < R; r += blockDim.x)
        g_bh[r * NB + blockIdx.x] = sh[r];
}

// ---------------- KS: etype scans (1 block) + zero BN accumulators -------
__global__ void __launch_bounds__(1024) ks_scan() {
    const int lane = threadIdx.x & 31;
    const int wid  = threadIdx.x >> 5;

    if (threadIdx.x < D) { g_sum[threadIdx.x] = 0.f; g_sumsq[threadIdx.x] = 0.f; }

    // ---- phase 1: per-relation totals (warp-per-relation reduce) ----
    for (int r = wid; r < R; r += 32) {
        int s = 0;
        for (int b = lane; b < NB; b += 32) s += g_bh[r * NB + b];
#pragma unroll
        for (int d = 16; d > 0; d >>= 1) s += __shfl_down_sync(FULL, s, d);
        if (lane == 0) g_hist[r] = s;
    }
    __syncthreads();

    // ---- phase 2: scan relation totals + chunk counts (warp 0) ----
    if (wid == 0) {
        int acc = 0, cacc = 0;
        for (int base = 0; base < R; base += 32) {
            int r = base + lane;
            int hv = (r < R) ? g_hist[r] : 0;
            int cv = (hv + 31) >> 5;
            int hs = hv, cs = cv;
#pragma unroll
            for (int d = 1; d < 32; d <<= 1) {
                int t1 = __shfl_up_sync(FULL, hs, d);
                int t2 = __shfl_up_sync(FULL, cs, d);
                if (lane >= d) { hs += t1; cs += t2; }
            }
            if (r < R) {
                g_off[r] = acc + hs - hv;
                g_chunkbase[r] = cacc + cs - cv;
            }
            acc  += __shfl_sync(FULL, hs, 31);
            cacc += __shfl_sync(FULL, cs, 31);
        }
        if (lane == 0) { g_off[R] = acc; g_chunkbase[R] = cacc; g_nchunk = cacc; }
    }
    __syncthreads();

    // ---- phase 3: per-relation scan over blocks (warp/relation) ----
    for (int r = wid; r < R; r += 32) {
        int carry = g_off[r];
        for (int b0 = 0; b0 < NB; b0 += 32) {
            int b = b0 + lane;
            int v = (b < NB) ? g_bh[r * NB + b] : 0;
            int s = v;
#pragma unroll
            for (int d = 1; d < 32; d <<= 1) {
                int t = __shfl_up_sync(FULL, s, d);
                if (lane >= d) s += t;
            }
            if (b < NB) g_boff[r * NB + b] = carry + s - v;
            carry += __shfl_sync(FULL, s, 31);
        }
    }
}

// ---------------- K3: etype scatter (src + dst payloads) ------------------
__global__ void __launch_bounds__(256) k3_scatter(
    const int* __restrict__ etype, const int* __restrict__ src,
    const int* __restrict__ dst)
{
    __shared__ int cur[R];
    for (int r = threadIdx.x; r < R; r += blockDim.x)
        cur[r] = g_boff[r * NB + blockIdx.x];
    __syncthreads();
    int base = blockIdx.x * EPB;
    for (int i = threadIdx.x; i < EPB; i += blockDim.x) {
        int e = base + i;
        int pos = atomicAdd(&cur[etype[e]], 1);    // shared, low contention
        g_ssrc[pos] = src[e];
        g_sdst[pos] = dst[e];
    }
}

// ---------------- K4: GEMV (FFMA2) + direct RED scatter into out ----------
// One warp = one 32-edge chunk of one relation. Raw relu outputs scatter
// via atomicAdd into out[dj*32+lane] — one contiguous 128B line per edge,
// same wavefront cost as the old g_msg store, but no second pass needed.
__global__ void __launch_bounds__(128, 8) k4_compute(
    const float* __restrict__ h, const float* __restrict__ weight,
    float* __restrict__ out)
{
    __shared__ __align__(16) float tile[4][32][32];
    __shared__ int s_cb[R + 1], s_off[R + 1];
    const int lane = threadIdx.x & 31;
    const int wid  = threadIdx.x >> 5;
    const int warp = (blockIdx.x * blockDim.x + threadIdx.x) >> 5;
    const int nwarp = (gridDim.x * blockDim.x) >> 5;

    for (int i = threadIdx.x; i <= R; i += blockDim.x) {
        s_cb[i] = g_chunkbase[i];
        s_off[i] = g_off[i];
    }
    __syncthreads();
    const int nchunk = g_nchunk;

    float lsum = 0.f, lsq = 0.f;

    for (int w = warp; w < nchunk; w += nwarp) {
        int lo2 = 0, hi2 = R;                      // largest r: cb[r] <= w
        while (lo2 < hi2) {
            int mid = (lo2 + hi2 + 1) >> 1;
            if (s_cb[mid] <= w) lo2 = mid; else hi2 = mid - 1;
        }
        int r = lo2;
        int s = s_off[r] + ((w - s_cb[r]) << 5);
        int n = min(32, s_off[r + 1] - s);

        // pack W columns for this lane into 16 b64 (f32x2) registers
        const float* wp = weight + r * (D * D) + lane;
        unsigned long long wc2[16];
#pragma unroll
        for (int k = 0; k < 16; k++) {
            float w0 = wp[(2 * k) * 32];
            float w1 = wp[(2 * k + 1) * 32];
            asm("mov.b64 %0, {%1, %2};" : "=l"(wc2[k]) : "f"(w0), "f"(w1));
        }

        int sj = 0, dj = 0;
        if (lane < n) { sj = g_ssrc[s + lane]; dj = g_sdst[s + lane]; }
        for (int j = 0; j < n; j++) {
            int sje = __shfl_sync(FULL, sj, j);
            tile[wid][j][lane] = h[sje * D + lane];   // coalesced 128B
        }
        __syncwarp();

        for (int j = 0; j < n; j++) {
            const ulonglong2* row = (const ulonglong2*)tile[wid][j];
            unsigned long long a0 = 0ull, a1 = 0ull, a2 = 0ull, a3 = 0ull;
#pragma unroll
            for (int kk = 0; kk < 4; kk++) {
                ulonglong2 q0 = row[2 * kk];          // LDS.128 broadcast
                ulonglong2 q1 = row[2 * kk + 1];
                asm("fma.rn.f32x2 %0, %1, %2, %0;" : "+l"(a0) : "l"(q0.x), "l"(wc2[4 * kk + 0]));
                asm("fma.rn.f32x2 %0, %1, %2, %0;" : "+l"(a1) : "l"(q0.y), "l"(wc2[4 * kk + 1]));
                asm("fma.rn.f32x2 %0, %1, %2, %0;" : "+l"(a2) : "l"(q1.x), "l"(wc2[4 * kk + 2]));
                asm("fma.rn.f32x2 %0, %1, %2, %0;" : "+l"(a3) : "l"(q1.y), "l"(wc2[4 * kk + 3]));
            }
            unsigned long long s01, s23, sT;
            asm("add.rn.f32x2 %0, %1, %2;" : "=l"(s01) : "l"(a0), "l"(a1));
            asm("add.rn.f32x2 %0, %1, %2;" : "=l"(s23) : "l"(a2), "l"(a3));
            asm("add.rn.f32x2 %0, %1, %2;" : "=l"(sT)  : "l"(s01), "l"(s23));
            float xlo, xhi;
            asm("mov.b64 {%0, %1}, %2;" : "=f"(xlo), "=f"(xhi) : "l"(sT));
            float acc = fmaxf(xlo + xhi, 0.f);
            lsum += acc;
            lsq = fmaf(acc, acc, lsq);
            int dpj = __shfl_sync(FULL, dj, j);
            atomicAdd(&out[dpj * D + lane], acc);     // 128B-line RED
        }
        __syncwarp();
    }
    __shared__ float ssum[4][32], ssq[4][32];
    ssum[wid][lane] = lsum; ssq[wid][lane] = lsq;
    __syncthreads();
    if (wid == 0) {
        float ts = ssum[0][lane] + ssum[1][lane] + ssum[2][lane] + ssum[3][lane];
        float tq = ssq[0][lane] + ssq[1][lane] + ssq[2][lane] + ssq[3][lane];
        atomicAdd(&g_sum[lane], ts);
        atomicAdd(&g_sumsq[lane], tq);
    }
}

// ---------------- K6: elementwise BN-normalize + mean (streaming) ---------
// out[n,d] = (sc_d * rawsum + cnt_n * shf_d) / max(cnt_n, 1)
// Also self-zeros g_dcnt for the next graph replay.
__global__ void __launch_bounds__(128) k6_finalize(
    float* __restrict__ out, const float* __restrict__ gamma,
    const float* __restrict__ beta)
{
    __shared__ float s_sc[32], s_sh[32];
    if (threadIdx.x < 32) {
        int d = threadIdx.x;
        float inv_e = 1.0f / (float)N_EDGES;
        float mu = g_sum[d] * inv_e;
        float var = fmaxf(g_sumsq[d] * inv_e - mu * mu, 0.f);
        float scale = rsqrtf(var + EPS) * gamma[d];
        s_sc[d] = scale;
        s_sh[d] = beta[d] - mu * scale;
    }
    __syncthreads();

    const int lane = threadIdx.x & 31;
    const int node = (blockIdx.x * blockDim.x + threadIdx.x) >> 5;
    if (node >= N_NODES) return;

    int cnt = g_dcnt[node];                       // all 32 lanes read
    __syncwarp();
    if (lane == 0) g_dcnt[node] = 0;              // self-zero for next replay

    float raw = out[node * D + lane];
    float v = 0.f;
    if (cnt > 0) {
        float fc = (float)cnt;
        v = (s_sc[lane] * raw + fc * s_sh[lane]) / fc;
    }
    out[node * D + lane] = v;
}

extern "C" void kernel_launch(void* const* d_in, const int* in_sizes, int n_in,
                              void* d_out, int out_size) {
    const float* h      = (const float*)d_in[0];
    const float* weight = (const float*)d_in[1];
    const float* gamma  = (const float*)d_in[2];
    const float* beta   = (const float*)d_in[3];
    const int*   src    = (const int*)d_in[4];
    const int*   dst    = (const int*)d_in[5];
    const int*   etype  = (const int*)d_in[6];
    float* out = (float*)d_out;

    k1_hist<<<NB, 256>>>(etype, dst, out);
    ks_scan<<<1, 1024>>>();
    k3_scatter<<<NB, 256>>>(etype, src, dst);
    k4_compute<<<1600, 128>>>(h, weight, out);
    k6_finalize<<<(N_NODES * 32 + 127) / 128, 128>>>(out, gamma, beta);
}

// round 17
// speedup vs baseline: 1.2841x; 1.0392x over previous
#include <cuda_runtime.h>

#define N_NODES 20000
#define N_EDGES 200000
#define D 32
#define R 100
#define EPS 1e-5f
#define NB 400          // histogram/scatter blocks
#define EPB 500         // edges per block (NB*EPB == N_EDGES)
#define FULL 0xffffffffu

// ---- PDL primitives ----
__device__ __forceinline__ void pdl_trigger() {
    asm volatile("griddepcontrol.launch_dependents;");
}
__device__ __forceinline__ void pdl_wait() {
    asm volatile("griddepcontrol.wait;" ::: "memory");
}

// ---------------- device scratch (static, no runtime allocation) --------
__device__ int   g_dcnt[N_NODES];           // per-dst counts (zeroed by k6)
__device__ int   g_bh[R * NB];              // per-(relation, block) histogram
__device__ int   g_boff[R * NB];            // per-(relation, block) base offset
__device__ int   g_hist[R];                 // per-relation totals
__device__ int   g_off[R + 1];              // relation bases
__device__ int   g_chunkbase[R + 1];        // chunk-count scan
__device__ int   g_ssrc[N_EDGES];           // src sorted by etype
__device__ int   g_sdst[N_EDGES];           // dst sorted by etype
__device__ float g_sum[D], g_sumsq[D];
__device__ int   g_nchunk;

// ---------------- K1: histograms + zero the output accumulator -----------
// Plain launch (full serialization vs previous replay). Triggers at top so
// ks can launch and run its independent prologue.
__global__ void __launch_bounds__(256) k1_hist(const int* __restrict__ etype,
                                               const int* __restrict__ dst,
                                               float* __restrict__ out) {
    pdl_trigger();
    __shared__ int sh[R];
    for (int i = threadIdx.x; i < R; i += blockDim.x) sh[i] = 0;
    // zero this block's slice of out (N_NODES*D / NB = 1600 floats)
    {
        float4* o4 = (float4*)(out) + blockIdx.x * 400;
        for (int i = threadIdx.x; i < 400; i += blockDim.x)
            o4[i] = make_float4(0.f, 0.f, 0.f, 0.f);
    }
    __syncthreads();
    int base = blockIdx.x * EPB;
    for (int i = threadIdx.x; i < EPB; i += blockDim.x) {
        atomicAdd(&sh[etype[base + i]], 1);
        atomicAdd(&g_dcnt[dst[base + i]], 1);   // 20K spread addrs: cheap
    }
    __syncthreads();
    for (int r = threadIdx.x; r < R; r += blockDim.x)
        g_bh[r * NB + blockIdx.x] = sh[r];
}

// ---------------- KS: etype scans (1 block), PDL on k1 --------------------
__global__ void __launch_bounds__(1024) ks_scan() {
    pdl_trigger();
    const int lane = threadIdx.x & 31;
    const int wid  = threadIdx.x >> 5;

    // independent prologue: zero BN accumulators (k4 consumes them later)
    if (threadIdx.x < D) { g_sum[threadIdx.x] = 0.f; g_sumsq[threadIdx.x] = 0.f; }

    pdl_wait();   // g_bh must be complete

    // ---- phase 1: per-relation totals (warp-per-relation reduce) ----
    for (int r = wid; r < R; r += 32) {
        int s = 0;
        for (int b = lane; b < NB; b += 32) s += g_bh[r * NB + b];
#pragma unroll
        for (int d = 16; d > 0; d >>= 1) s += __shfl_down_sync(FULL, s, d);
        if (lane == 0) g_hist[r] = s;
    }
    __syncthreads();

    // ---- phase 2: scan relation totals + chunk counts (warp 0) ----
    if (wid == 0) {
        int acc = 0, cacc = 0;
        for (int base = 0; base < R; base += 32) {
            int r = base + lane;
            int hv = (r < R) ? g_hist[r] : 0;
            int cv = (hv + 31) >> 5;
            int hs = hv, cs = cv;
#pragma unroll
            for (int d = 1; d < 32; d <<= 1) {
                int t1 = __shfl_up_sync(FULL, hs, d);
                int t2 = __shfl_up_sync(FULL, cs, d);
                if (lane >= d) { hs += t1; cs += t2; }
            }
            if (r < R) {
                g_off[r] = acc + hs - hv;
                g_chunkbase[r] = cacc + cs - cv;
            }
            acc  += __shfl_sync(FULL, hs, 31);
            cacc += __shfl_sync(FULL, cs, 31);
        }
        if (lane == 0) { g_off[R] = acc; g_chunkbase[R] = cacc; g_nchunk = cacc; }
    }
    __syncthreads();

    // ---- phase 3: per-relation scan over blocks (warp/relation) ----
    for (int r = wid; r < R; r += 32) {
        int carry = g_off[r];
        for (int b0 = 0; b0 < NB; b0 += 32) {
            int b = b0 + lane;
            int v = (b < NB) ? g_bh[r * NB + b] : 0;
            int s = v;
#pragma unroll
            for (int d = 1; d < 32; d <<= 1) {
                int t = __shfl_up_sync(FULL, s, d);
                if (lane >= d) s += t;
            }
            if (b < NB) g_boff[r * NB + b] = carry + s - v;
            carry += __shfl_sync(FULL, s, 31);
        }
    }
}

// ---------------- K3: etype scatter, PDL on ks ----------------------------
// Prologue loads this thread's edge payloads into registers (pure input
// reads) while ks is still running; the wait covers g_boff.
__global__ void __launch_bounds__(256) k3_scatter(
    const int* __restrict__ etype, const int* __restrict__ src,
    const int* __restrict__ dst)
{
    pdl_trigger();
    __shared__ int cur[R];
    int base = blockIdx.x * EPB;
    int t = threadIdx.x;
    // independent prologue: register-load both edges per thread (MLP=6)
    int e0 = base + t, e1 = base + t + 256;
    bool p1 = (t + 256 < EPB);
    int et0 = etype[e0], s0 = src[e0], d0 = dst[e0];
    int et1 = 0, s1 = 0, d1 = 0;
    if (p1) { et1 = etype[e1]; s1 = src[e1]; d1 = dst[e1]; }

    pdl_wait();   // g_boff must be complete

    for (int r = t; r < R; r += blockDim.x)
        cur[r] = g_boff[r * NB + blockIdx.x];
    __syncthreads();
    int pos0 = atomicAdd(&cur[et0], 1);
    g_ssrc[pos0] = s0;
    g_sdst[pos0] = d0;
    if (p1) {
        int pos1 = atomicAdd(&cur[et1], 1);
        g_ssrc[pos1] = s1;
        g_sdst[pos1] = d1;
    }
}

// ---------------- K4: GEMV (FFMA2) + direct RED scatter, PDL on k3 --------
__global__ void __launch_bounds__(128, 8) k4_compute(
    const float* __restrict__ h, const float* __restrict__ weight,
    float* __restrict__ out)
{
    pdl_trigger();
    __shared__ __align__(16) float tile[4][32][32];
    __shared__ int s_cb[R + 1], s_off[R + 1];
    const int lane = threadIdx.x & 31;
    const int wid  = threadIdx.x >> 5;
    const int warp = (blockIdx.x * blockDim.x + threadIdx.x) >> 5;
    const int nwarp = (gridDim.x * blockDim.x) >> 5;

    pdl_wait();   // needs ks tables + k3 sorted arrays (transitively ordered)

    for (int i = threadIdx.x; i <= R; i += blockDim.x) {
        s_cb[i] = g_chunkbase[i];
        s_off[i] = g_off[i];
    }
    __syncthreads();
    const int nchunk = g_nchunk;

    float lsum = 0.f, lsq = 0.f;

    for (int w = warp; w < nchunk; w += nwarp) {
        int lo2 = 0, hi2 = R;                      // largest r: cb[r] <= w
        while (lo2 < hi2) {
            int mid = (lo2 + hi2 + 1) >> 1;
            if (s_cb[mid] <= w) lo2 = mid; else hi2 = mid - 1;
        }
        int r = lo2;
        int s = s_off[r] + ((w - s_cb[r]) << 5);
        int n = min(32, s_off[r + 1] - s);

        // pack W columns for this lane into 16 b64 (f32x2) registers
        const float* wp = weight + r * (D * D) + lane;
        unsigned long long wc2[16];
#pragma unroll
        for (int k = 0; k < 16; k++) {
            float w0 = wp[(2 * k) * 32];
            float w1 = wp[(2 * k + 1) * 32];
            asm("mov.b64 %0, {%1, %2};" : "=l"(wc2[k]) : "f"(w0), "f"(w1));
        }

        int sj = 0, dj = 0;
        if (lane < n) { sj = g_ssrc[s + lane]; dj = g_sdst[s + lane]; }
        for (int j = 0; j < n; j++) {
            int sje = __shfl_sync(FULL, sj, j);
            tile[wid][j][lane] = h[sje * D + lane];   // coalesced 128B
        }
        __syncwarp();

        for (int j = 0; j < n; j++) {
            const ulonglong2* row = (const ulonglong2*)tile[wid][j];
            unsigned long long a0 = 0ull, a1 = 0ull, a2 = 0ull, a3 = 0ull;
#pragma unroll
            for (int kk = 0; kk < 4; kk++) {
                ulonglong2 q0 = row[2 * kk];          // LDS.128 broadcast
                ulonglong2 q1 = row[2 * kk + 1];
                asm("fma.rn.f32x2 %0, %1, %2, %0;" : "+l"(a0) : "l"(q0.x), "l"(wc2[4 * kk + 0]));
                asm("fma.rn.f32x2 %0, %1, %2, %0;" : "+l"(a1) : "l"(q0.y), "l"(wc2[4 * kk + 1]));
                asm("fma.rn.f32x2 %0, %1, %2, %0;" : "+l"(a2) : "l"(q1.x), "l"(wc2[4 * kk + 2]));
                asm("fma.rn.f32x2 %0, %1, %2, %0;" : "+l"(a3) : "l"(q1.y), "l"(wc2[4 * kk + 3]));
            }
            unsigned long long s01, s23, sT;
            asm("add.rn.f32x2 %0, %1, %2;" : "=l"(s01) : "l"(a0), "l"(a1));
            asm("add.rn.f32x2 %0, %1, %2;" : "=l"(s23) : "l"(a2), "l"(a3));
            asm("add.rn.f32x2 %0, %1, %2;" : "=l"(sT)  : "l"(s01), "l"(s23));
            float xlo, xhi;
            asm("mov.b64 {%0, %1}, %2;" : "=f"(xlo), "=f"(xhi) : "l"(sT));
            float acc = fmaxf(xlo + xhi, 0.f);
            lsum += acc;
            lsq = fmaf(acc, acc, lsq);
            int dpj = __shfl_sync(FULL, dj, j);
            atomicAdd(&out[dpj * D + lane], acc);     // 128B-line RED
        }
        __syncwarp();
    }
    __shared__ float ssum[4][32], ssq[4][32];
    ssum[wid][lane] = lsum; ssq[wid][lane] = lsq;
    __syncthreads();
    if (wid == 0) {
        float ts = ssum[0][lane] + ssum[1][lane] + ssum[2][lane] + ssum[3][lane];
        float tq = ssq[0][lane] + ssq[1][lane] + ssq[2][lane] + ssq[3][lane];
        atomicAdd(&g_sum[lane], ts);
        atomicAdd(&g_sumsq[lane], tq);
    }
}

// ---------------- K6: elementwise BN-normalize + mean, PDL on k4 ----------
__global__ void __launch_bounds__(128) k6_finalize(
    float* __restrict__ out, const float* __restrict__ gamma,
    const float* __restrict__ beta)
{
    pdl_trigger();
    __shared__ float s_sc[32], s_sh[32];
    // independent prologue: load gamma/beta (pure input reads)
    float gv = 0.f, bv = 0.f;
    if (threadIdx.x < 32) { gv = gamma[threadIdx.x]; bv = beta[threadIdx.x]; }

    pdl_wait();   // g_sum/g_sumsq/out raw sums must be complete

    if (threadIdx.x < 32) {
        int d = threadIdx.x;
        float inv_e = 1.0f / (float)N_EDGES;
        float mu = g_sum[d] * inv_e;
        float var = fmaxf(g_sumsq[d] * inv_e - mu * mu, 0.f);
        float scale = rsqrtf(var + EPS) * gv;
        s_sc[d] = scale;
        s_sh[d] = bv - mu * scale;
    }
    __syncthreads();

    const int lane = threadIdx.x & 31;
    const int node = (blockIdx.x * blockDim.x + threadIdx.x) >> 5;
    if (node >= N_NODES) return;

    int cnt = g_dcnt[node];                       // all 32 lanes read
    __syncwarp();
    if (lane == 0) g_dcnt[node] = 0;              // self-zero for next replay

    float raw = out[node * D + lane];
    float v = 0.f;
    if (cnt > 0) {
        float fc = (float)cnt;
        v = (s_sc[lane] * raw + fc * s_sh[lane]) / fc;
    }
    out[node * D + lane] = v;
}

// ---------------- host: PDL launches ------------------------------------
static inline void launch_pdl(const void* fn, dim3 grid, dim3 block, void** args) {
    cudaLaunchConfig_t cfg = {};
    cfg.gridDim = grid;
    cfg.blockDim = block;
    cfg.dynamicSmemBytes = 0;
    cfg.stream = 0;                         // legacy default stream (captured)
    cudaLaunchAttribute attr;
    attr.id = cudaLaunchAttributeProgrammaticStreamSerialization;
    attr.val.programmaticStreamSerializationAllowed = 1;
    cfg.attrs = &attr;
    cfg.numAttrs = 1;
    cudaLaunchKernelExC(&cfg, fn, args);
}

extern "C" void kernel_launch(void* const* d_in, const int* in_sizes, int n_in,
                              void* d_out, int out_size) {
    const float* h      = (const float*)d_in[0];
    const float* weight = (const float*)d_in[1];
    const float* gamma  = (const float*)d_in[2];
    const float* beta   = (const float*)d_in[3];
    const int*   src    = (const int*)d_in[4];
    const int*   dst    = (const int*)d_in[5];
    const int*   etype  = (const int*)d_in[6];
    float* out = (float*)d_out;

    // k1: plain launch — full serialization vs previous replay's k6
    k1_hist<<<NB, 256>>>(etype, dst, out);

    {   // ks: PDL on k1
        void* args[] = {};
        launch_pdl((const void*)ks_scan, dim3(1), dim3(1024), args);
    }
    {   // k3: PDL on ks
        void* args[] = {(void*)&etype, (void*)&src, (void*)&dst};
        launch_pdl((const void*)k3_scatter, dim3(NB), dim3(256), args);
    }
    {   // k4: PDL on k3
        void* args[] = {(void*)&h, (void*)&weight, (void*)&out};
        launch_pdl((const void*)k4_compute, dim3(1600), dim3(128), args);
    }
    {   // k6: PDL on k4
        void* args[] = {(void*)&out, (void*)&gamma, (void*)&beta};
        launch_pdl((const void*)k6_finalize, dim3((N_NODES * 32 + 127) / 128), dim3(128), args);
    }
}